// round 2
// baseline (speedup 1.0000x reference)
#include <cuda_runtime.h>
#include <cuda_bf16.h>
#include <cstdint>

// Problem constants (fixed by the dataset)
#define MAXN 100000
#define MAXE 1600000
#define MAXETOT (MAXN + MAXE)
#define FDIM 256      // input dim
#define HC   128      // H*C output channels
#define YW   256      // y row width: [xl(128) | xr(128)]

// ---------------- scratch (device globals; no allocation allowed) -------------
__device__ float g_y[(size_t)MAXN * YW];     // projected features [N][256]
__device__ int   g_deg[MAXN];
__device__ int   g_incl[MAXN];
__device__ int   g_sums[1024];
__device__ int   g_rowptr[MAXN + 1];
__device__ int   g_cursor[MAXN];
__device__ int   g_csr[MAXETOT];

// ---------------- GEMM: y = x @ [Wl;Wr]^T + [bl;br] ---------------------------
// M x 256 @ 256 x 256 -> M x 256.  BM=128, BN=128, BK=16, 256 threads, 8x8/thread.
#define BM 128
#define BN 128
#define BK 16

__global__ __launch_bounds__(256) void gemm_kernel(
    const float* __restrict__ x,
    const float* __restrict__ Wl, const float* __restrict__ bl,
    const float* __restrict__ Wr, const float* __restrict__ br,
    int M)
{
    __shared__ float As[BK][BM + 4];
    __shared__ float Bs[BK][BN + 4];

    const int tid = threadIdx.x;
    const int m0 = blockIdx.x * BM;
    const int n0 = blockIdx.y * BN;
    const int tm = tid >> 4;      // 0..15
    const int tn = tid & 15;      // 0..15

    float acc[8][8];
#pragma unroll
    for (int i = 0; i < 8; i++)
#pragma unroll
        for (int j = 0; j < 8; j++) acc[i][j] = 0.f;

    for (int k0 = 0; k0 < FDIM; k0 += BK) {
        // Load A tile (x[m0..m0+128, k0..k0+16]) transposed into As[k][m]
#pragma unroll
        for (int l = 0; l < 2; l++) {
            int id = tid * 2 + l;          // 0..511
            int row = id >> 2;             // 0..127
            int c4 = (id & 3) * 4;         // 0,4,8,12
            int gm = m0 + row;
            if (gm >= M) gm = M - 1;       // clamp; stores are guarded later
            float4 v = *(const float4*)&x[(size_t)gm * FDIM + k0 + c4];
            As[c4 + 0][row] = v.x;
            As[c4 + 1][row] = v.y;
            As[c4 + 2][row] = v.z;
            As[c4 + 3][row] = v.w;
        }
        // Load B tile (Wc[n0..n0+128, k0..k0+16]) into Bs[k][n]
#pragma unroll
        for (int l = 0; l < 2; l++) {
            int id = tid * 2 + l;
            int n = id >> 2;               // 0..127
            int c4 = (id & 3) * 4;
            int gn = n0 + n;
            const float* Wrow = (gn < HC) ? &Wl[(size_t)gn * FDIM]
                                          : &Wr[(size_t)(gn - HC) * FDIM];
            float4 v = *(const float4*)&Wrow[k0 + c4];
            Bs[c4 + 0][n] = v.x;
            Bs[c4 + 1][n] = v.y;
            Bs[c4 + 2][n] = v.z;
            Bs[c4 + 3][n] = v.w;
        }
        __syncthreads();

#pragma unroll
        for (int kk = 0; kk < BK; kk++) {
            float a[8], b[8];
            ((float4*)a)[0] = *(const float4*)&As[kk][tm * 8];
            ((float4*)a)[1] = *(const float4*)&As[kk][tm * 8 + 4];
            ((float4*)b)[0] = *(const float4*)&Bs[kk][tn * 8];
            ((float4*)b)[1] = *(const float4*)&Bs[kk][tn * 8 + 4];
#pragma unroll
            for (int i = 0; i < 8; i++)
#pragma unroll
                for (int j = 0; j < 8; j++)
                    acc[i][j] = fmaf(a[i], b[j], acc[i][j]);
        }
        __syncthreads();
    }

    // Epilogue: add bias, store to g_y
#pragma unroll
    for (int i = 0; i < 8; i++) {
        int gm = m0 + tm * 8 + i;
        if (gm >= M) continue;
#pragma unroll
        for (int j = 0; j < 8; j++) {
            int gn = n0 + tn * 8 + j;
            float bv = (gn < HC) ? bl[gn] : br[gn - HC];
            g_y[(size_t)gm * YW + gn] = acc[i][j] + bv;
        }
    }
}

// ---------------- CSR build ---------------------------------------------------
__global__ void init_deg_kernel(int N) {
    int i = blockIdx.x * blockDim.x + threadIdx.x;
    if (i < N) g_deg[i] = 1;   // self loop
}

__global__ void hist_kernel(const int* __restrict__ ei, int E) {
    int e = blockIdx.x * blockDim.x + threadIdx.x;
    if (e < E) atomicAdd(&g_deg[ei[E + e]], 1);
}

__global__ void scan1_kernel(int n) {
    __shared__ int s[1024];
    int i = blockIdx.x * 1024 + threadIdx.x;
    int v = (i < n) ? g_deg[i] : 0;
    s[threadIdx.x] = v;
    __syncthreads();
    for (int off = 1; off < 1024; off <<= 1) {
        int t = (threadIdx.x >= off) ? s[threadIdx.x - off] : 0;
        __syncthreads();
        s[threadIdx.x] += t;
        __syncthreads();
    }
    if (i < n) g_incl[i] = s[threadIdx.x];
    if (threadIdx.x == 1023) g_sums[blockIdx.x] = s[1023];
}

__global__ void scan2_kernel(int nc) {
    __shared__ int s[1024];
    int v = (threadIdx.x < nc) ? g_sums[threadIdx.x] : 0;
    s[threadIdx.x] = v;
    __syncthreads();
    for (int off = 1; off < 1024; off <<= 1) {
        int t = (threadIdx.x >= off) ? s[threadIdx.x - off] : 0;
        __syncthreads();
        s[threadIdx.x] += t;
        __syncthreads();
    }
    if (threadIdx.x < nc)
        g_sums[threadIdx.x] = threadIdx.x ? s[threadIdx.x - 1] : 0;
}

__global__ void scan3_kernel(int n, int etot) {
    int i = blockIdx.x * 1024 + threadIdx.x;
    if (i < n) {
        int excl = g_incl[i] - g_deg[i] + g_sums[blockIdx.x];
        g_rowptr[i] = excl;
        g_cursor[i] = excl;
        if (i == n - 1) g_rowptr[n] = etot;
    }
}

__global__ void scatter_kernel(const int* __restrict__ ei, int E, int N) {
    int e = blockIdx.x * blockDim.x + threadIdx.x;
    int etot = E + N;
    if (e >= etot) return;
    int s, d;
    if (e < E) { s = ei[e]; d = ei[E + e]; }
    else       { s = d = e - E; }
    int pos = atomicAdd(&g_cursor[d], 1);
    g_csr[pos] = s;
}

// ---------------- main GATv2 edge pass: one warp per destination node --------
// logits, softmax (no max-subtraction; |logit| <~ 8 so exp is safe) and
// weighted aggregation fused in a single pass over CSR edges.
__global__ __launch_bounds__(256) void gat_edge_kernel(
    const float* __restrict__ att, const float* __restrict__ bias,
    float* __restrict__ out, int N)
{
    const int warp = (blockIdx.x * blockDim.x + threadIdx.x) >> 5;
    const int lane = threadIdx.x & 31;
    if (warp >= N) return;
    const int n = warp;

    // lane covers channels [4*lane, 4*lane+4): lanes 0-15 head 0, 16-31 head 1
    const float4 xrv  = *(const float4*)&g_y[(size_t)n * YW + HC + lane * 4];
    const float4 attv = ((const float4*)att)[lane];

    const int base = g_rowptr[n];
    const int end  = g_rowptr[n + 1];

    float denom = 0.f;
    float4 acc = make_float4(0.f, 0.f, 0.f, 0.f);

    for (int i0 = base; i0 < end; i0 += 32) {
        int cnt = min(32, end - i0);
        int si = 0;
        if (lane < cnt) si = g_csr[i0 + lane];
#pragma unroll 1
        for (int j = 0; j < cnt; j++) {
            int s = __shfl_sync(0xffffffffu, si, j);
            float4 xv = *(const float4*)&g_y[(size_t)s * YW + lane * 4];
            float e0 = xv.x + xrv.x;
            float e1 = xv.y + xrv.y;
            float e2 = xv.z + xrv.z;
            float e3 = xv.w + xrv.w;
            float l0 = e0 > 0.f ? e0 : 0.2f * e0;
            float l1 = e1 > 0.f ? e1 : 0.2f * e1;
            float l2 = e2 > 0.f ? e2 : 0.2f * e2;
            float l3 = e3 > 0.f ? e3 : 0.2f * e3;
            float part = l0 * attv.x;
            part = fmaf(l1, attv.y, part);
            part = fmaf(l2, attv.z, part);
            part = fmaf(l3, attv.w, part);
            // reduce within each 16-lane head group (xor offsets < 16)
            part += __shfl_xor_sync(0xffffffffu, part, 1);
            part += __shfl_xor_sync(0xffffffffu, part, 2);
            part += __shfl_xor_sync(0xffffffffu, part, 4);
            part += __shfl_xor_sync(0xffffffffu, part, 8);
            float p = __expf(part);
            denom += p;
            acc.x = fmaf(p, xv.x, acc.x);
            acc.y = fmaf(p, xv.y, acc.y);
            acc.z = fmaf(p, xv.z, acc.z);
            acc.w = fmaf(p, xv.w, acc.w);
        }
    }

    float rd = 1.0f / denom;
    float4 bv = ((const float4*)bias)[lane];
    float4 o;
    o.x = fmaf(acc.x, rd, bv.x);
    o.y = fmaf(acc.y, rd, bv.y);
    o.z = fmaf(acc.z, rd, bv.z);
    o.w = fmaf(acc.w, rd, bv.w);
    *(float4*)&out[(size_t)n * HC + lane * 4] = o;
}

// ---------------- launch ------------------------------------------------------
extern "C" void kernel_launch(void* const* d_in, const int* in_sizes, int n_in,
                              void* d_out, int out_size)
{
    const float* x    = (const float*)d_in[0];
    const float* Wl   = (const float*)d_in[1];
    const float* bl   = (const float*)d_in[2];
    const float* Wr   = (const float*)d_in[3];
    const float* br   = (const float*)d_in[4];
    const float* att  = (const float*)d_in[5];
    const float* bias = (const float*)d_in[6];
    const int*   ei   = (const int*)d_in[7];
    float* out = (float*)d_out;

    const int N = in_sizes[0] / FDIM;
    const int E = in_sizes[7] / 2;
    const int Etot = E + N;
    if (N > MAXN || E > MAXE) return;  // scratch sized for the fixed problem

    // 1) projection GEMM
    dim3 ggrid((N + BM - 1) / BM, YW / BN);
    gemm_kernel<<<ggrid, 256>>>(x, Wl, bl, Wr, br, N);

    // 2) CSR build (degree -> scan -> scatter)
    init_deg_kernel<<<(N + 255) / 256, 256>>>(N);
    hist_kernel<<<(E + 255) / 256, 256>>>(ei, E);
    int nChunks = (N + 1023) / 1024;
    scan1_kernel<<<nChunks, 1024>>>(N);
    scan2_kernel<<<1, 1024>>>(nChunks);
    scan3_kernel<<<nChunks, 1024>>>(N, Etot);
    scatter_kernel<<<(Etot + 255) / 256, 256>>>(ei, E, N);

    // 3) fused attention softmax + aggregation, one warp per node
    int nWarpsBlocks = (N * 32 + 255) / 256;
    gat_edge_kernel<<<nWarpsBlocks, 256>>>(att, bias, out, N);
}

// round 4
// speedup vs baseline: 1.6881x; 1.6881x over previous
#include <cuda_runtime.h>
#include <cuda_bf16.h>
#include <cstdint>

// Problem constants (fixed by the dataset)
#define MAXN 100000
#define MAXE 1600000
#define MAXETOT (MAXN + MAXE)
#define FDIM 256      // input dim
#define HC   128      // H*C output channels

// ---------------- scratch (device globals; no allocation allowed) -------------
__device__ float    g_xl[(size_t)MAXN * HC];   // lin_l projection (gathered by edges)
__device__ float    g_xr[(size_t)MAXN * HC];   // lin_r projection (per dst node)
__device__ unsigned g_wt[256 * 256];           // W^T as tf32 bits: [k][n], n<128 -> Wl
__device__ int      g_deg[MAXN];
__device__ int      g_incl[MAXN];
__device__ int      g_sums[1024];
__device__ int      g_rowptr[MAXN + 1];
__device__ int      g_cursor[MAXN];
__device__ int      g_csr[MAXETOT];

// ---------------- tf32 helpers ------------------------------------------------
__device__ __forceinline__ unsigned f2tf32(float x) {
    unsigned r;
    asm("cvt.rna.tf32.f32 %0, %1;" : "=r"(r) : "f"(x));
    return r;
}

__device__ __forceinline__ void mma_tf32(float* d, const unsigned* a, const unsigned* b) {
    asm("mma.sync.aligned.m16n8k8.row.col.f32.tf32.tf32.f32 "
        "{%0,%1,%2,%3}, {%4,%5,%6,%7}, {%8,%9}, {%0,%1,%2,%3};"
        : "+f"(d[0]), "+f"(d[1]), "+f"(d[2]), "+f"(d[3])
        : "r"(a[0]), "r"(a[1]), "r"(a[2]), "r"(a[3]), "r"(b[0]), "r"(b[1]));
}

// ---------------- W transpose + tf32 convert (tiny: 256x256) ------------------
__global__ void transpose_w_kernel(const float* __restrict__ Wl,
                                   const float* __restrict__ Wr) {
    int n = threadIdx.x;   // output channel 0..255
    int k = blockIdx.x;    // input channel 0..255
    float v = (n < HC) ? Wl[n * FDIM + k] : Wr[(n - HC) * FDIM + k];
    g_wt[k * 256 + n] = f2tf32(v);
}

// ---------------- tf32 tensor-core GEMM ---------------------------------------
// y[M,256] = x[M,256] @ Wc^T (+bias), split-stored to g_xl / g_xr.
// BM=128, BN=256 (full width), BK=16. 512 threads = 16 warps (4x4),
// warp tile 32x64 via m16n8k8: Mtiles=2, Ntiles=8, 64 fp32 acc/thread.
#define GBM 128
#define GBK 16

__global__ __launch_bounds__(512, 1) void gemm_tc_kernel(
    const float* __restrict__ x,
    const float* __restrict__ bl, const float* __restrict__ br,
    int M)
{
    __shared__ unsigned As[GBM][20];    // [m][k], stride 20: frag loads conflict-free
    __shared__ unsigned Bs[GBK][264];   // [k][n], stride 264 (== 8 mod 32): conflict-free

    const int tid  = threadIdx.x;
    const int m0   = blockIdx.x * GBM;
    const int w    = tid >> 5;
    const int lane = tid & 31;
    const int wm   = w >> 2;            // 0..3 -> m offset wm*32
    const int wn   = w & 3;             // 0..3 -> n offset wn*64
    const int gid  = lane >> 2;         // 0..7
    const int tig  = lane & 3;          // 0..3

    float acc[2][8][4];
#pragma unroll
    for (int mt = 0; mt < 2; mt++)
#pragma unroll
        for (int nt = 0; nt < 8; nt++)
#pragma unroll
            for (int c = 0; c < 4; c++) acc[mt][nt][c] = 0.f;

    // A-tile load mapping: thread -> (row ml, 4-col chunk ac4)
    const int ml  = tid >> 2;           // 0..127
    const int ac4 = (tid & 3) * 4;      // 0,4,8,12
    const int gm  = min(m0 + ml, M - 1);
    const float* arow = x + (size_t)gm * FDIM + ac4;

    // B-tile load mapping: 1024 uint4 per tile, 2 per thread
    const int bkk0 = tid >> 6;               // 0..7   (row pair base)
    const int bn4  = (tid & 63) << 2;        // 0..252 (n start, x4)

    for (int it = 0; it < FDIM / GBK; ++it) {
        const int k0 = it * GBK;

        // stage loads in registers (overlaps previous iteration's MMAs)
        float4 av = *(const float4*)(arow + k0);
        uint4 bv0 = *(const uint4*)&g_wt[(k0 + bkk0) * 256 + bn4];
        uint4 bv1 = *(const uint4*)&g_wt[(k0 + bkk0 + 8) * 256 + bn4];

        __syncthreads();   // previous compute done before overwrite

        {
            uint4 at;
            at.x = f2tf32(av.x); at.y = f2tf32(av.y);
            at.z = f2tf32(av.z); at.w = f2tf32(av.w);
            *(uint4*)&As[ml][ac4] = at;
            *(uint4*)&Bs[bkk0][bn4]     = bv0;
            *(uint4*)&Bs[bkk0 + 8][bn4] = bv1;
        }
        __syncthreads();

#pragma unroll
        for (int ks8 = 0; ks8 < 2; ks8++) {
            const int ks = ks8 * 8;
            unsigned afr[2][4];
#pragma unroll
            for (int mt = 0; mt < 2; mt++) {
                int r = wm * 32 + mt * 16 + gid;
                afr[mt][0] = As[r][ks + tig];
                afr[mt][1] = As[r + 8][ks + tig];
                afr[mt][2] = As[r][ks + tig + 4];
                afr[mt][3] = As[r + 8][ks + tig + 4];
            }
#pragma unroll
            for (int nt = 0; nt < 8; nt++) {
                int cn = wn * 64 + nt * 8 + gid;
                unsigned bfr[2];
                bfr[0] = Bs[ks + tig][cn];
                bfr[1] = Bs[ks + tig + 4][cn];
                mma_tf32(acc[0][nt], afr[0], bfr);
                mma_tf32(acc[1][nt], afr[1], bfr);
            }
        }
    }

    // Epilogue: bias add, split-store to g_xl / g_xr
#pragma unroll
    for (int mt = 0; mt < 2; mt++) {
        const int mrow0 = m0 + wm * 32 + mt * 16 + gid;
        const int mrow1 = mrow0 + 8;
#pragma unroll
        for (int nt = 0; nt < 8; nt++) {
            const int n = wn * 64 + nt * 8 + tig * 2;
            float* dst;
            const float* bb;
            int nn;
            if (n < HC) { dst = g_xl; bb = bl; nn = n; }
            else        { dst = g_xr; bb = br; nn = n - HC; }
            const float b0 = bb[nn], b1 = bb[nn + 1];
            if (mrow0 < M) {
                float2 v; v.x = acc[mt][nt][0] + b0; v.y = acc[mt][nt][1] + b1;
                *(float2*)&dst[(size_t)mrow0 * HC + nn] = v;
            }
            if (mrow1 < M) {
                float2 v; v.x = acc[mt][nt][2] + b0; v.y = acc[mt][nt][3] + b1;
                *(float2*)&dst[(size_t)mrow1 * HC + nn] = v;
            }
        }
    }
}

// ---------------- CSR build ---------------------------------------------------
__global__ void init_deg_kernel(int N) {
    int i = blockIdx.x * blockDim.x + threadIdx.x;
    if (i < N) g_deg[i] = 1;   // self loop
}

__global__ void hist_kernel(const int* __restrict__ ei, int E) {
    int e = blockIdx.x * blockDim.x + threadIdx.x;
    if (e < E) atomicAdd(&g_deg[ei[E + e]], 1);
}

__global__ void scan1_kernel(int n) {
    __shared__ int s[1024];
    int i = blockIdx.x * 1024 + threadIdx.x;
    int v = (i < n) ? g_deg[i] : 0;
    s[threadIdx.x] = v;
    __syncthreads();
    for (int off = 1; off < 1024; off <<= 1) {
        int t = (threadIdx.x >= off) ? s[threadIdx.x - off] : 0;
        __syncthreads();
        s[threadIdx.x] += t;
        __syncthreads();
    }
    if (i < n) g_incl[i] = s[threadIdx.x];
    if (threadIdx.x == 1023) g_sums[blockIdx.x] = s[1023];
}

__global__ void scan2_kernel(int nc) {
    __shared__ int s[1024];
    int v = (threadIdx.x < nc) ? g_sums[threadIdx.x] : 0;
    s[threadIdx.x] = v;
    __syncthreads();
    for (int off = 1; off < 1024; off <<= 1) {
        int t = (threadIdx.x >= off) ? s[threadIdx.x - off] : 0;
        __syncthreads();
        s[threadIdx.x] += t;
        __syncthreads();
    }
    if (threadIdx.x < nc)
        g_sums[threadIdx.x] = threadIdx.x ? s[threadIdx.x - 1] : 0;
}

__global__ void scan3_kernel(int n, int etot) {
    int i = blockIdx.x * 1024 + threadIdx.x;
    if (i < n) {
        int excl = g_incl[i] - g_deg[i] + g_sums[blockIdx.x];
        g_rowptr[i] = excl;
        g_cursor[i] = excl;
        if (i == n - 1) g_rowptr[n] = etot;
    }
}

__global__ void scatter_kernel(const int* __restrict__ ei, int E, int N) {
    int e = blockIdx.x * blockDim.x + threadIdx.x;
    int etot = E + N;
    if (e >= etot) return;
    int s, d;
    if (e < E) { s = ei[e]; d = ei[E + e]; }
    else       { s = d = e - E; }
    int pos = atomicAdd(&g_cursor[d], 1);
    g_csr[pos] = s;
}

// ---------------- main GATv2 edge pass: one warp per destination node --------
__global__ __launch_bounds__(256) void gat_edge_kernel(
    const float* __restrict__ att, const float* __restrict__ bias,
    float* __restrict__ out, int N)
{
    const int warp = (blockIdx.x * blockDim.x + threadIdx.x) >> 5;
    const int lane = threadIdx.x & 31;
    if (warp >= N) return;
    const int n = warp;

    // lane covers channels [4*lane, 4*lane+4): lanes 0-15 head 0, 16-31 head 1
    const float4 xrv  = *(const float4*)&g_xr[(size_t)n * HC + lane * 4];
    const float4 attv = ((const float4*)att)[lane];

    const int base = g_rowptr[n];
    const int end  = g_rowptr[n + 1];

    float denom = 0.f;
    float4 acc = make_float4(0.f, 0.f, 0.f, 0.f);

    for (int i0 = base; i0 < end; i0 += 32) {
        int cnt = min(32, end - i0);
        int si = 0;
        if (lane < cnt) si = g_csr[i0 + lane];
#pragma unroll 1
        for (int j = 0; j < cnt; j++) {
            int s = __shfl_sync(0xffffffffu, si, j);
            float4 xv = *(const float4*)&g_xl[(size_t)s * HC + lane * 4];
            float e0 = xv.x + xrv.x;
            float e1 = xv.y + xrv.y;
            float e2 = xv.z + xrv.z;
            float e3 = xv.w + xrv.w;
            float l0 = e0 > 0.f ? e0 : 0.2f * e0;
            float l1 = e1 > 0.f ? e1 : 0.2f * e1;
            float l2 = e2 > 0.f ? e2 : 0.2f * e2;
            float l3 = e3 > 0.f ? e3 : 0.2f * e3;
            float part = l0 * attv.x;
            part = fmaf(l1, attv.y, part);
            part = fmaf(l2, attv.z, part);
            part = fmaf(l3, attv.w, part);
            // reduce within each 16-lane head group (xor offsets < 16)
            part += __shfl_xor_sync(0xffffffffu, part, 1);
            part += __shfl_xor_sync(0xffffffffu, part, 2);
            part += __shfl_xor_sync(0xffffffffu, part, 4);
            part += __shfl_xor_sync(0xffffffffu, part, 8);
            float p = __expf(part);
            denom += p;
            acc.x = fmaf(p, xv.x, acc.x);
            acc.y = fmaf(p, xv.y, acc.y);
            acc.z = fmaf(p, xv.z, acc.z);
            acc.w = fmaf(p, xv.w, acc.w);
        }
    }

    float rd = 1.0f / denom;
    float4 bv = ((const float4*)bias)[lane];
    float4 o;
    o.x = fmaf(acc.x, rd, bv.x);
    o.y = fmaf(acc.y, rd, bv.y);
    o.z = fmaf(acc.z, rd, bv.z);
    o.w = fmaf(acc.w, rd, bv.w);
    *(float4*)&out[(size_t)n * HC + lane * 4] = o;
}

// ---------------- launch ------------------------------------------------------
extern "C" void kernel_launch(void* const* d_in, const int* in_sizes, int n_in,
                              void* d_out, int out_size)
{
    const float* x    = (const float*)d_in[0];
    const float* Wl   = (const float*)d_in[1];
    const float* bl   = (const float*)d_in[2];
    const float* Wr   = (const float*)d_in[3];
    const float* br   = (const float*)d_in[4];
    const float* att  = (const float*)d_in[5];
    const float* bias = (const float*)d_in[6];
    const int*   ei   = (const int*)d_in[7];
    float* out = (float*)d_out;

    const int N = in_sizes[0] / FDIM;
    const int E = in_sizes[7] / 2;
    const int Etot = E + N;
    if (N > MAXN || E > MAXE) return;  // scratch sized for the fixed problem

    // 1) projection GEMM on tensor cores (tf32)
    transpose_w_kernel<<<256, 256>>>(Wl, Wr);
    gemm_tc_kernel<<<(N + GBM - 1) / GBM, 512>>>(x, bl, br, N);

    // 2) CSR build (degree -> scan -> scatter)
    init_deg_kernel<<<(N + 255) / 256, 256>>>(N);
    hist_kernel<<<(E + 255) / 256, 256>>>(ei, E);
    int nChunks = (N + 1023) / 1024;
    scan1_kernel<<<nChunks, 1024>>>(N);
    scan2_kernel<<<1, 1024>>>(nChunks);
    scan3_kernel<<<nChunks, 1024>>>(N, Etot);
    scatter_kernel<<<(Etot + 255) / 256, 256>>>(ei, E, N);

    // 3) fused attention softmax + aggregation, one warp per node
    int nWarpsBlocks = (N * 32 + 255) / 256;
    gat_edge_kernel<<<nWarpsBlocks, 256>>>(att, bias, out, N);
}

// round 5
// speedup vs baseline: 1.8047x; 1.0691x over previous
#include <cuda_runtime.h>
#include <cuda_bf16.h>
#include <cuda_fp16.h>
#include <cstdint>

// Problem constants (fixed by the dataset)
#define MAXN 100000
#define MAXE 1600000
#define MAXETOT (MAXN + MAXE)
#define FDIM 256      // input dim
#define HC   128      // H*C output channels

// ---------------- scratch (device globals; no allocation allowed) -------------
__device__ __half    g_xlh[(size_t)MAXN * HC];  // lin_l projection, fp16 (edge gather)
__device__ float     g_xr[(size_t)MAXN * HC];   // lin_r projection, fp32 (per dst node)
__device__ unsigned  g_wt[256 * 256];           // W^T as tf32 bits: [k][n], n<128 -> Wl
__device__ int       g_deg[MAXN];
__device__ int       g_incl[MAXN];
__device__ int       g_sums[1024];
__device__ int       g_rowptr[MAXN + 1];
__device__ int       g_cursor[MAXN];
__device__ int       g_csr[MAXETOT];

// ---------------- tf32 helpers ------------------------------------------------
__device__ __forceinline__ unsigned f2tf32(float x) {
    unsigned r;
    asm("cvt.rna.tf32.f32 %0, %1;" : "=r"(r) : "f"(x));
    return r;
}

__device__ __forceinline__ void mma_tf32(float* d, const unsigned* a, const unsigned* b) {
    asm("mma.sync.aligned.m16n8k8.row.col.f32.tf32.tf32.f32 "
        "{%0,%1,%2,%3}, {%4,%5,%6,%7}, {%8,%9}, {%0,%1,%2,%3};"
        : "+f"(d[0]), "+f"(d[1]), "+f"(d[2]), "+f"(d[3])
        : "r"(a[0]), "r"(a[1]), "r"(a[2]), "r"(a[3]), "r"(b[0]), "r"(b[1]));
}

// ---------------- W transpose + tf32 convert (tiny: 256x256) ------------------
__global__ void transpose_w_kernel(const float* __restrict__ Wl,
                                   const float* __restrict__ Wr) {
    int n = threadIdx.x;   // output channel 0..255
    int k = blockIdx.x;    // input channel 0..255
    float v = (n < HC) ? Wl[n * FDIM + k] : Wr[(n - HC) * FDIM + k];
    g_wt[k * 256 + n] = f2tf32(v);
}

// ---------------- tf32 tensor-core GEMM ---------------------------------------
// y[M,256] = x[M,256] @ Wc^T (+bias); xl half -> g_xlh, xr fp32 -> g_xr.
#define GBM 128
#define GBK 16

__global__ __launch_bounds__(512, 1) void gemm_tc_kernel(
    const float* __restrict__ x,
    const float* __restrict__ bl, const float* __restrict__ br,
    int M)
{
    __shared__ unsigned As[GBM][20];    // [m][k], stride 20: frag loads conflict-free
    __shared__ unsigned Bs[GBK][264];   // [k][n], stride 264 (== 8 mod 32): conflict-free

    const int tid  = threadIdx.x;
    const int m0   = blockIdx.x * GBM;
    const int w    = tid >> 5;
    const int lane = tid & 31;
    const int wm   = w >> 2;            // 0..3 -> m offset wm*32
    const int wn   = w & 3;             // 0..3 -> n offset wn*64
    const int gid  = lane >> 2;         // 0..7
    const int tig  = lane & 3;          // 0..3

    float acc[2][8][4];
#pragma unroll
    for (int mt = 0; mt < 2; mt++)
#pragma unroll
        for (int nt = 0; nt < 8; nt++)
#pragma unroll
            for (int c = 0; c < 4; c++) acc[mt][nt][c] = 0.f;

    const int ml  = tid >> 2;           // 0..127
    const int ac4 = (tid & 3) * 4;      // 0,4,8,12
    const int gm  = min(m0 + ml, M - 1);
    const float* arow = x + (size_t)gm * FDIM + ac4;

    const int bkk0 = tid >> 6;               // 0..7
    const int bn4  = (tid & 63) << 2;        // 0..252

    for (int it = 0; it < FDIM / GBK; ++it) {
        const int k0 = it * GBK;

        float4 av = *(const float4*)(arow + k0);
        uint4 bv0 = *(const uint4*)&g_wt[(k0 + bkk0) * 256 + bn4];
        uint4 bv1 = *(const uint4*)&g_wt[(k0 + bkk0 + 8) * 256 + bn4];

        __syncthreads();

        {
            uint4 at;
            at.x = f2tf32(av.x); at.y = f2tf32(av.y);
            at.z = f2tf32(av.z); at.w = f2tf32(av.w);
            *(uint4*)&As[ml][ac4] = at;
            *(uint4*)&Bs[bkk0][bn4]     = bv0;
            *(uint4*)&Bs[bkk0 + 8][bn4] = bv1;
        }
        __syncthreads();

#pragma unroll
        for (int ks8 = 0; ks8 < 2; ks8++) {
            const int ks = ks8 * 8;
            unsigned afr[2][4];
#pragma unroll
            for (int mt = 0; mt < 2; mt++) {
                int r = wm * 32 + mt * 16 + gid;
                afr[mt][0] = As[r][ks + tig];
                afr[mt][1] = As[r + 8][ks + tig];
                afr[mt][2] = As[r][ks + tig + 4];
                afr[mt][3] = As[r + 8][ks + tig + 4];
            }
#pragma unroll
            for (int nt = 0; nt < 8; nt++) {
                int cn = wn * 64 + nt * 8 + gid;
                unsigned bfr[2];
                bfr[0] = Bs[ks + tig][cn];
                bfr[1] = Bs[ks + tig + 4][cn];
                mma_tf32(acc[0][nt], afr[0], bfr);
                mma_tf32(acc[1][nt], afr[1], bfr);
            }
        }
    }

    // Epilogue: bias add; xl -> fp16, xr -> fp32
#pragma unroll
    for (int mt = 0; mt < 2; mt++) {
        const int mrow0 = m0 + wm * 32 + mt * 16 + gid;
        const int mrow1 = mrow0 + 8;
#pragma unroll
        for (int nt = 0; nt < 8; nt++) {
            const int n = wn * 64 + nt * 8 + tig * 2;
            if (n < HC) {
                const float b0 = bl[n], b1 = bl[n + 1];
                if (mrow0 < M) {
                    __half2 h = __floats2half2_rn(acc[mt][nt][0] + b0, acc[mt][nt][1] + b1);
                    *(__half2*)&g_xlh[(size_t)mrow0 * HC + n] = h;
                }
                if (mrow1 < M) {
                    __half2 h = __floats2half2_rn(acc[mt][nt][2] + b0, acc[mt][nt][3] + b1);
                    *(__half2*)&g_xlh[(size_t)mrow1 * HC + n] = h;
                }
            } else {
                const int nn = n - HC;
                const float b0 = br[nn], b1 = br[nn + 1];
                if (mrow0 < M) {
                    float2 v; v.x = acc[mt][nt][0] + b0; v.y = acc[mt][nt][1] + b1;
                    *(float2*)&g_xr[(size_t)mrow0 * HC + nn] = v;
                }
                if (mrow1 < M) {
                    float2 v; v.x = acc[mt][nt][2] + b0; v.y = acc[mt][nt][3] + b1;
                    *(float2*)&g_xr[(size_t)mrow1 * HC + nn] = v;
                }
            }
        }
    }
}

// ---------------- CSR build ---------------------------------------------------
__global__ void init_deg_kernel(int N) {
    int i = blockIdx.x * blockDim.x + threadIdx.x;
    if (i < N) g_deg[i] = 1;   // self loop
}

__global__ void hist_kernel(const int* __restrict__ ei, int E) {
    int e = blockIdx.x * blockDim.x + threadIdx.x;
    if (e < E) atomicAdd(&g_deg[ei[E + e]], 1);
}

__global__ void scan1_kernel(int n) {
    __shared__ int s[1024];
    int i = blockIdx.x * 1024 + threadIdx.x;
    int v = (i < n) ? g_deg[i] : 0;
    s[threadIdx.x] = v;
    __syncthreads();
    for (int off = 1; off < 1024; off <<= 1) {
        int t = (threadIdx.x >= off) ? s[threadIdx.x - off] : 0;
        __syncthreads();
        s[threadIdx.x] += t;
        __syncthreads();
    }
    if (i < n) g_incl[i] = s[threadIdx.x];
    if (threadIdx.x == 1023) g_sums[blockIdx.x] = s[1023];
}

__global__ void scan2_kernel(int nc) {
    __shared__ int s[1024];
    int v = (threadIdx.x < nc) ? g_sums[threadIdx.x] : 0;
    s[threadIdx.x] = v;
    __syncthreads();
    for (int off = 1; off < 1024; off <<= 1) {
        int t = (threadIdx.x >= off) ? s[threadIdx.x - off] : 0;
        __syncthreads();
        s[threadIdx.x] += t;
        __syncthreads();
    }
    if (threadIdx.x < nc)
        g_sums[threadIdx.x] = threadIdx.x ? s[threadIdx.x - 1] : 0;
}

__global__ void scan3_kernel(int n, int etot) {
    int i = blockIdx.x * 1024 + threadIdx.x;
    if (i < n) {
        int excl = g_incl[i] - g_deg[i] + g_sums[blockIdx.x];
        g_rowptr[i] = excl;
        g_cursor[i] = excl;
        if (i == n - 1) g_rowptr[n] = etot;
    }
}

__global__ void scatter_kernel(const int* __restrict__ ei, int E, int N) {
    int e = blockIdx.x * blockDim.x + threadIdx.x;
    int etot = E + N;
    if (e >= etot) return;
    int s, d;
    if (e < E) { s = ei[e]; d = ei[E + e]; }
    else       { s = d = e - E; }
    int pos = atomicAdd(&g_cursor[d], 1);
    g_csr[pos] = s;
}

// ---------------- GATv2 edge pass: one warp per node, 2 edges per step --------
// 16 lanes x 8 fp16 channels cover a full xl row; lanes 0-15 process edge j,
// lanes 16-31 edge j+1. Reduction: 3 shfl_xor in 8-lane head groups per pair,
// cross-half combine once per node at the end.
__global__ __launch_bounds__(256) void gat_edge_kernel(
    const float* __restrict__ att, const float* __restrict__ bias,
    float* __restrict__ out, int N)
{
    const int warp = (blockIdx.x * blockDim.x + threadIdx.x) >> 5;
    const int lane = threadIdx.x & 31;
    if (warp >= N) return;
    const int n   = warp;
    const int sub = lane >> 4;      // which edge of the pair
    const int sl  = lane & 15;      // 16-lane subgroup lane; channels [8*sl, 8*sl+8)
                                    // sl 0-7 -> head 0, sl 8-15 -> head 1

    float xr[8], at[8];
    {
        float4 v0 = *(const float4*)&g_xr[(size_t)n * HC + sl * 8];
        float4 v1 = *(const float4*)&g_xr[(size_t)n * HC + sl * 8 + 4];
        xr[0]=v0.x; xr[1]=v0.y; xr[2]=v0.z; xr[3]=v0.w;
        xr[4]=v1.x; xr[5]=v1.y; xr[6]=v1.z; xr[7]=v1.w;
        float4 a0 = *(const float4*)&att[sl * 8];
        float4 a1 = *(const float4*)&att[sl * 8 + 4];
        at[0]=a0.x; at[1]=a0.y; at[2]=a0.z; at[3]=a0.w;
        at[4]=a1.x; at[5]=a1.y; at[6]=a1.z; at[7]=a1.w;
    }

    const int base = g_rowptr[n];
    const int end  = g_rowptr[n + 1];

    float denom = 0.f;
    float acc[8];
#pragma unroll
    for (int k = 0; k < 8; k++) acc[k] = 0.f;

    for (int i0 = base; i0 < end; i0 += 32) {
        const int cnt = min(32, end - i0);
        int si = 0;
        if (lane < cnt) si = g_csr[i0 + lane];
#pragma unroll 1
        for (int jp = 0; jp < cnt; jp += 2) {
            const int idx = jp + sub;
            const bool valid = idx < cnt;
            const int s = __shfl_sync(0xffffffffu, si, valid ? idx : cnt - 1);

            uint4 hv = *(const uint4*)&g_xlh[(size_t)s * HC + sl * 8];
            float f[8];
            {
                float2 p0 = __half22float2(*(__half2*)&hv.x);
                float2 p1 = __half22float2(*(((__half2*)&hv.x) + 1));
                float2 p2 = __half22float2(*(__half2*)&hv.z);
                float2 p3 = __half22float2(*(((__half2*)&hv.z) + 1));
                f[0]=p0.x; f[1]=p0.y; f[2]=p1.x; f[3]=p1.y;
                f[4]=p2.x; f[5]=p2.y; f[6]=p3.x; f[7]=p3.y;
            }

            float part = 0.f;
#pragma unroll
            for (int k = 0; k < 8; k++) {
                float e = f[k] + xr[k];
                float l = e > 0.f ? e : 0.2f * e;
                part = fmaf(l, at[k], part);
            }
            // reduce over 8-lane head group
            part += __shfl_xor_sync(0xffffffffu, part, 1);
            part += __shfl_xor_sync(0xffffffffu, part, 2);
            part += __shfl_xor_sync(0xffffffffu, part, 4);

            float p = valid ? __expf(part) : 0.f;
            denom += p;
#pragma unroll
            for (int k = 0; k < 8; k++) acc[k] = fmaf(p, f[k], acc[k]);
        }
    }

    // combine the two edge-halves of the warp
    denom += __shfl_xor_sync(0xffffffffu, denom, 16);
#pragma unroll
    for (int k = 0; k < 8; k++) acc[k] += __shfl_xor_sync(0xffffffffu, acc[k], 16);

    if (sub == 0) {
        const float rd = 1.0f / denom;
        float4 b0 = *(const float4*)&bias[sl * 8];
        float4 b1 = *(const float4*)&bias[sl * 8 + 4];
        float4 o0, o1;
        o0.x = fmaf(acc[0], rd, b0.x); o0.y = fmaf(acc[1], rd, b0.y);
        o0.z = fmaf(acc[2], rd, b0.z); o0.w = fmaf(acc[3], rd, b0.w);
        o1.x = fmaf(acc[4], rd, b1.x); o1.y = fmaf(acc[5], rd, b1.y);
        o1.z = fmaf(acc[6], rd, b1.z); o1.w = fmaf(acc[7], rd, b1.w);
        *(float4*)&out[(size_t)n * HC + sl * 8]     = o0;
        *(float4*)&out[(size_t)n * HC + sl * 8 + 4] = o1;
    }
}

// ---------------- launch ------------------------------------------------------
extern "C" void kernel_launch(void* const* d_in, const int* in_sizes, int n_in,
                              void* d_out, int out_size)
{
    const float* x    = (const float*)d_in[0];
    const float* Wl   = (const float*)d_in[1];
    const float* bl   = (const float*)d_in[2];
    const float* Wr   = (const float*)d_in[3];
    const float* br   = (const float*)d_in[4];
    const float* att  = (const float*)d_in[5];
    const float* bias = (const float*)d_in[6];
    const int*   ei   = (const int*)d_in[7];
    float* out = (float*)d_out;

    const int N = in_sizes[0] / FDIM;
    const int E = in_sizes[7] / 2;
    const int Etot = E + N;
    if (N > MAXN || E > MAXE) return;  // scratch sized for the fixed problem

    // Lazily created host-side resources (first call = non-captured correctness
    // run; no device memory involved).
    static cudaStream_t s_side = nullptr;
    static cudaEvent_t  ev_fork = nullptr, ev_join = nullptr;
    if (!s_side) {
        cudaStreamCreateWithFlags(&s_side, cudaStreamNonBlocking);
        cudaEventCreateWithFlags(&ev_fork, cudaEventDisableTiming);
        cudaEventCreateWithFlags(&ev_join, cudaEventDisableTiming);
    }

    // Fork: CSR build on side stream (depends only on edge_index)
    cudaEventRecord(ev_fork, 0);
    cudaStreamWaitEvent(s_side, ev_fork, 0);

    init_deg_kernel<<<(N + 255) / 256, 256, 0, s_side>>>(N);
    hist_kernel<<<(E + 255) / 256, 256, 0, s_side>>>(ei, E);
    int nChunks = (N + 1023) / 1024;
    scan1_kernel<<<nChunks, 1024, 0, s_side>>>(N);
    scan2_kernel<<<1, 1024, 0, s_side>>>(nChunks);
    scan3_kernel<<<nChunks, 1024, 0, s_side>>>(N, Etot);
    scatter_kernel<<<(Etot + 255) / 256, 256, 0, s_side>>>(ei, E, N);
    cudaEventRecord(ev_join, s_side);

    // Main stream: projection GEMM on tensor cores (tf32)
    transpose_w_kernel<<<256, 256>>>(Wl, Wr);
    gemm_tc_kernel<<<(N + GBM - 1) / GBM, 512>>>(x, bl, br, N);

    // Join, then fused attention softmax + aggregation
    cudaStreamWaitEvent(0, ev_join, 0);
    int nWarpsBlocks = (N * 32 + 255) / 256;
    gat_edge_kernel<<<nWarpsBlocks, 256>>>(att, bias, out, N);
}

// round 6
// speedup vs baseline: 1.8188x; 1.0078x over previous
#include <cuda_runtime.h>
#include <cuda_bf16.h>
#include <cuda_fp16.h>
#include <cstdint>

// Problem constants (fixed by the dataset)
#define MAXN 100000
#define MAXE 1600000
#define MAXETOT (MAXN + MAXE)
#define FDIM 256      // input dim
#define HC   128      // H*C output channels

// ---------------- scratch (device globals; no allocation allowed) -------------
__device__ __half    g_xlh[(size_t)MAXN * HC];  // lin_l projection, fp16 (edge gather)
__device__ float     g_xr[(size_t)MAXN * HC];   // lin_r projection, fp32 (per dst node)
__device__ unsigned  g_wt[256 * 256];           // W^T as tf32 bits: [k][n], n<128 -> Wl
__device__ int       g_deg[MAXN];
__device__ int       g_incl[MAXN];
__device__ int       g_sums[1024];
__device__ int       g_rowptr[MAXN + 1];
__device__ int       g_cursor[MAXN];
__device__ int       g_csr[MAXETOT];

// ---------------- tf32 helpers ------------------------------------------------
__device__ __forceinline__ unsigned f2tf32(float x) {
    unsigned r;
    asm("cvt.rna.tf32.f32 %0, %1;" : "=r"(r) : "f"(x));
    return r;
}

__device__ __forceinline__ void mma_tf32(float* d, const unsigned* a, const unsigned* b) {
    asm("mma.sync.aligned.m16n8k8.row.col.f32.tf32.tf32.f32 "
        "{%0,%1,%2,%3}, {%4,%5,%6,%7}, {%8,%9}, {%0,%1,%2,%3};"
        : "+f"(d[0]), "+f"(d[1]), "+f"(d[2]), "+f"(d[3])
        : "r"(a[0]), "r"(a[1]), "r"(a[2]), "r"(a[3]), "r"(b[0]), "r"(b[1]));
}

// ---------------- W transpose + tf32 convert (tiny: 256x256) ------------------
__global__ void transpose_w_kernel(const float* __restrict__ Wl,
                                   const float* __restrict__ Wr) {
    int n = threadIdx.x;   // output channel 0..255
    int k = blockIdx.x;    // input channel 0..255
    float v = (n < HC) ? Wl[n * FDIM + k] : Wr[(n - HC) * FDIM + k];
    g_wt[k * 256 + n] = f2tf32(v);
}

// ---------------- tf32 tensor-core GEMM (double-buffered) ---------------------
// y[M,256] = x[M,256] @ Wc^T (+bias); xl half -> g_xlh, xr fp32 -> g_xr.
// BM=128, BN=256, BK=16, 512 threads = 16 warps (4x4), warp tile 32x64.
// Ping-pong smem: 1 barrier per K-iter; next-tile LDGs overlap current MMAs.
#define GBM 128
#define GBK 16
#define AS_STRIDE 20    // conflict-free fragment reads
#define BS_STRIDE 264   // == 8 mod 32: conflict-free
#define AS_WORDS (GBM * AS_STRIDE)          // 2560
#define BS_WORDS (GBK * BS_STRIDE)          // 4224
#define GEMM_SMEM_BYTES ((2 * AS_WORDS + 2 * BS_WORDS) * 4)   // 54272

__global__ __launch_bounds__(512, 1) void gemm_tc_kernel(
    const float* __restrict__ x,
    const float* __restrict__ bl, const float* __restrict__ br,
    int M)
{
    extern __shared__ unsigned smem_dyn[];
    unsigned* AsBuf[2] = { smem_dyn, smem_dyn + AS_WORDS };
    unsigned* BsBuf[2] = { smem_dyn + 2 * AS_WORDS, smem_dyn + 2 * AS_WORDS + BS_WORDS };

    const int tid  = threadIdx.x;
    const int m0   = blockIdx.x * GBM;
    const int w    = tid >> 5;
    const int lane = tid & 31;
    const int wm   = w >> 2;            // 0..3 -> m offset wm*32
    const int wn   = w & 3;             // 0..3 -> n offset wn*64
    const int gid  = lane >> 2;         // 0..7
    const int tig  = lane & 3;          // 0..3

    float acc[2][8][4];
#pragma unroll
    for (int mt = 0; mt < 2; mt++)
#pragma unroll
        for (int nt = 0; nt < 8; nt++)
#pragma unroll
            for (int c = 0; c < 4; c++) acc[mt][nt][c] = 0.f;

    // A-tile load mapping: thread -> (row ml, 4-col chunk ac4)
    const int ml  = tid >> 2;           // 0..127
    const int ac4 = (tid & 3) * 4;      // 0,4,8,12
    const int gm  = min(m0 + ml, M - 1);
    const float* arow = x + (size_t)gm * FDIM + ac4;

    // B-tile load mapping: 1024 uint4 per tile, 2 per thread
    const int bkk0 = tid >> 6;               // 0..7
    const int bn4  = (tid & 63) << 2;        // 0..252

    // ---- preload tile 0 into buffer 0
    {
        float4 av = *(const float4*)(arow);
        uint4 bv0 = *(const uint4*)&g_wt[(bkk0) * 256 + bn4];
        uint4 bv1 = *(const uint4*)&g_wt[(bkk0 + 8) * 256 + bn4];
        uint4 at;
        at.x = f2tf32(av.x); at.y = f2tf32(av.y);
        at.z = f2tf32(av.z); at.w = f2tf32(av.w);
        *(uint4*)&AsBuf[0][ml * AS_STRIDE + ac4] = at;
        *(uint4*)&BsBuf[0][bkk0 * BS_STRIDE + bn4]       = bv0;
        *(uint4*)&BsBuf[0][(bkk0 + 8) * BS_STRIDE + bn4] = bv1;
    }
    __syncthreads();

    const int NIT = FDIM / GBK;   // 16
    for (int it = 0; it < NIT; ++it) {
        const unsigned* As = AsBuf[it & 1];
        const unsigned* Bs = BsBuf[it & 1];

        // issue next tile's global loads early (drain under the MMAs below)
        float4 av; uint4 bv0, bv1;
        if (it + 1 < NIT) {
            const int k0 = (it + 1) * GBK;
            av  = *(const float4*)(arow + k0);
            bv0 = *(const uint4*)&g_wt[(k0 + bkk0) * 256 + bn4];
            bv1 = *(const uint4*)&g_wt[(k0 + bkk0 + 8) * 256 + bn4];
        }

#pragma unroll
        for (int ks8 = 0; ks8 < 2; ks8++) {
            const int ks = ks8 * 8;
            unsigned afr[2][4];
#pragma unroll
            for (int mt = 0; mt < 2; mt++) {
                int r = wm * 32 + mt * 16 + gid;
                afr[mt][0] = As[r * AS_STRIDE + ks + tig];
                afr[mt][1] = As[(r + 8) * AS_STRIDE + ks + tig];
                afr[mt][2] = As[r * AS_STRIDE + ks + tig + 4];
                afr[mt][3] = As[(r + 8) * AS_STRIDE + ks + tig + 4];
            }
#pragma unroll
            for (int nt = 0; nt < 8; nt++) {
                int cn = wn * 64 + nt * 8 + gid;
                unsigned bfr[2];
                bfr[0] = Bs[(ks + tig) * BS_STRIDE + cn];
                bfr[1] = Bs[(ks + tig + 4) * BS_STRIDE + cn];
                mma_tf32(acc[0][nt], afr[0], bfr);
                mma_tf32(acc[1][nt], afr[1], bfr);
            }
        }

        if (it + 1 < NIT) {
            unsigned* Asn = AsBuf[(it + 1) & 1];
            unsigned* Bsn = BsBuf[(it + 1) & 1];
            uint4 at;
            at.x = f2tf32(av.x); at.y = f2tf32(av.y);
            at.z = f2tf32(av.z); at.w = f2tf32(av.w);
            *(uint4*)&Asn[ml * AS_STRIDE + ac4] = at;
            *(uint4*)&Bsn[bkk0 * BS_STRIDE + bn4]       = bv0;
            *(uint4*)&Bsn[(bkk0 + 8) * BS_STRIDE + bn4] = bv1;
            __syncthreads();
        }
    }

    // Epilogue: bias add; xl -> fp16, xr -> fp32
#pragma unroll
    for (int mt = 0; mt < 2; mt++) {
        const int mrow0 = m0 + wm * 32 + mt * 16 + gid;
        const int mrow1 = mrow0 + 8;
#pragma unroll
        for (int nt = 0; nt < 8; nt++) {
            const int n = wn * 64 + nt * 8 + tig * 2;
            if (n < HC) {
                const float b0 = bl[n], b1 = bl[n + 1];
                if (mrow0 < M) {
                    __half2 h = __floats2half2_rn(acc[mt][nt][0] + b0, acc[mt][nt][1] + b1);
                    *(__half2*)&g_xlh[(size_t)mrow0 * HC + n] = h;
                }
                if (mrow1 < M) {
                    __half2 h = __floats2half2_rn(acc[mt][nt][2] + b0, acc[mt][nt][3] + b1);
                    *(__half2*)&g_xlh[(size_t)mrow1 * HC + n] = h;
                }
            } else {
                const int nn = n - HC;
                const float b0 = br[nn], b1 = br[nn + 1];
                if (mrow0 < M) {
                    float2 v; v.x = acc[mt][nt][0] + b0; v.y = acc[mt][nt][1] + b1;
                    *(float2*)&g_xr[(size_t)mrow0 * HC + nn] = v;
                }
                if (mrow1 < M) {
                    float2 v; v.x = acc[mt][nt][2] + b0; v.y = acc[mt][nt][3] + b1;
                    *(float2*)&g_xr[(size_t)mrow1 * HC + nn] = v;
                }
            }
        }
    }
}

// ---------------- CSR build ---------------------------------------------------
__global__ void init_deg_kernel(int N) {
    int i = blockIdx.x * blockDim.x + threadIdx.x;
    if (i < N) g_deg[i] = 1;   // self loop
}

__global__ void hist_kernel(const int* __restrict__ ei, int E) {
    int e = blockIdx.x * blockDim.x + threadIdx.x;
    if (e < E) atomicAdd(&g_deg[ei[E + e]], 1);
}

__global__ void scan1_kernel(int n) {
    __shared__ int s[1024];
    int i = blockIdx.x * 1024 + threadIdx.x;
    int v = (i < n) ? g_deg[i] : 0;
    s[threadIdx.x] = v;
    __syncthreads();
    for (int off = 1; off < 1024; off <<= 1) {
        int t = (threadIdx.x >= off) ? s[threadIdx.x - off] : 0;
        __syncthreads();
        s[threadIdx.x] += t;
        __syncthreads();
    }
    if (i < n) g_incl[i] = s[threadIdx.x];
    if (threadIdx.x == 1023) g_sums[blockIdx.x] = s[1023];
}

__global__ void scan2_kernel(int nc) {
    __shared__ int s[1024];
    int v = (threadIdx.x < nc) ? g_sums[threadIdx.x] : 0;
    s[threadIdx.x] = v;
    __syncthreads();
    for (int off = 1; off < 1024; off <<= 1) {
        int t = (threadIdx.x >= off) ? s[threadIdx.x - off] : 0;
        __syncthreads();
        s[threadIdx.x] += t;
        __syncthreads();
    }
    if (threadIdx.x < nc)
        g_sums[threadIdx.x] = threadIdx.x ? s[threadIdx.x - 1] : 0;
}

__global__ void scan3_kernel(int n, int etot) {
    int i = blockIdx.x * 1024 + threadIdx.x;
    if (i < n) {
        int excl = g_incl[i] - g_deg[i] + g_sums[blockIdx.x];
        g_rowptr[i] = excl;
        g_cursor[i] = excl;
        if (i == n - 1) g_rowptr[n] = etot;
    }
}

__global__ void scatter_kernel(const int* __restrict__ ei, int E, int N) {
    int e = blockIdx.x * blockDim.x + threadIdx.x;
    int etot = E + N;
    if (e >= etot) return;
    int s, d;
    if (e < E) { s = ei[e]; d = ei[E + e]; }
    else       { s = d = e - E; }
    int pos = atomicAdd(&g_cursor[d], 1);
    g_csr[pos] = s;
}

// ---------------- GATv2 edge pass: warp per node, 2 edges/step, pipelined -----
__global__ __launch_bounds__(256) void gat_edge_kernel(
    const float* __restrict__ att, const float* __restrict__ bias,
    float* __restrict__ out, int N)
{
    const int warp = (blockIdx.x * blockDim.x + threadIdx.x) >> 5;
    const int lane = threadIdx.x & 31;
    if (warp >= N) return;
    const int n   = warp;
    const int sub = lane >> 4;      // which edge of the pair
    const int sl  = lane & 15;      // channels [8*sl, 8*sl+8); sl<8 head0, else head1

    float xr[8], at[8];
    {
        float4 v0 = *(const float4*)&g_xr[(size_t)n * HC + sl * 8];
        float4 v1 = *(const float4*)&g_xr[(size_t)n * HC + sl * 8 + 4];
        xr[0]=v0.x; xr[1]=v0.y; xr[2]=v0.z; xr[3]=v0.w;
        xr[4]=v1.x; xr[5]=v1.y; xr[6]=v1.z; xr[7]=v1.w;
        float4 a0 = *(const float4*)&att[sl * 8];
        float4 a1 = *(const float4*)&att[sl * 8 + 4];
        at[0]=a0.x; at[1]=a0.y; at[2]=a0.z; at[3]=a0.w;
        at[4]=a1.x; at[5]=a1.y; at[6]=a1.z; at[7]=a1.w;
    }

    const int base = g_rowptr[n];
    const int end  = g_rowptr[n + 1];

    float denom = 0.f;
    float acc[8];
#pragma unroll
    for (int k = 0; k < 8; k++) acc[k] = 0.f;

    for (int i0 = base; i0 < end; i0 += 32) {
        const int cnt = min(32, end - i0);
        int si = 0;
        if (lane < cnt) si = g_csr[i0 + lane];

        // prefetch pair 0
        int s0 = __shfl_sync(0xffffffffu, si, (sub < cnt) ? sub : 0);
        uint4 hv = *(const uint4*)&g_xlh[(size_t)s0 * HC + sl * 8];

#pragma unroll 1
        for (int jp = 0; jp < cnt; jp += 2) {
            const bool valid = (jp + sub) < cnt;

            // prefetch next pair's row segment (overlaps compute below)
            const int nidx = jp + 2 + sub;
            const int sn = __shfl_sync(0xffffffffu, si, (nidx < cnt) ? nidx : 0);
            uint4 hvn = hv;
            if (jp + 2 < cnt) hvn = *(const uint4*)&g_xlh[(size_t)sn * HC + sl * 8];

            float f[8];
            {
                float2 p0 = __half22float2(*(__half2*)&hv.x);
                float2 p1 = __half22float2(*(((__half2*)&hv.x) + 1));
                float2 p2 = __half22float2(*(__half2*)&hv.z);
                float2 p3 = __half22float2(*(((__half2*)&hv.z) + 1));
                f[0]=p0.x; f[1]=p0.y; f[2]=p1.x; f[3]=p1.y;
                f[4]=p2.x; f[5]=p2.y; f[6]=p3.x; f[7]=p3.y;
            }

            float part = 0.f;
#pragma unroll
            for (int k = 0; k < 8; k++) {
                float e = f[k] + xr[k];
                float l = e > 0.f ? e : 0.2f * e;
                part = fmaf(l, at[k], part);
            }
            // reduce over 8-lane head group
            part += __shfl_xor_sync(0xffffffffu, part, 1);
            part += __shfl_xor_sync(0xffffffffu, part, 2);
            part += __shfl_xor_sync(0xffffffffu, part, 4);

            float p = valid ? __expf(part) : 0.f;
            denom += p;
#pragma unroll
            for (int k = 0; k < 8; k++) acc[k] = fmaf(p, f[k], acc[k]);

            hv = hvn;
        }
    }

    // combine the two edge-halves of the warp
    denom += __shfl_xor_sync(0xffffffffu, denom, 16);
#pragma unroll
    for (int k = 0; k < 8; k++) acc[k] += __shfl_xor_sync(0xffffffffu, acc[k], 16);

    if (sub == 0) {
        const float rd = 1.0f / denom;
        float4 b0 = *(const float4*)&bias[sl * 8];
        float4 b1 = *(const float4*)&bias[sl * 8 + 4];
        float4 o0, o1;
        o0.x = fmaf(acc[0], rd, b0.x); o0.y = fmaf(acc[1], rd, b0.y);
        o0.z = fmaf(acc[2], rd, b0.z); o0.w = fmaf(acc[3], rd, b0.w);
        o1.x = fmaf(acc[4], rd, b1.x); o1.y = fmaf(acc[5], rd, b1.y);
        o1.z = fmaf(acc[6], rd, b1.z); o1.w = fmaf(acc[7], rd, b1.w);
        *(float4*)&out[(size_t)n * HC + sl * 8]     = o0;
        *(float4*)&out[(size_t)n * HC + sl * 8 + 4] = o1;
    }
}

// ---------------- launch ------------------------------------------------------
extern "C" void kernel_launch(void* const* d_in, const int* in_sizes, int n_in,
                              void* d_out, int out_size)
{
    const float* x    = (const float*)d_in[0];
    const float* Wl   = (const float*)d_in[1];
    const float* bl   = (const float*)d_in[2];
    const float* Wr   = (const float*)d_in[3];
    const float* br   = (const float*)d_in[4];
    const float* att  = (const float*)d_in[5];
    const float* bias = (const float*)d_in[6];
    const int*   ei   = (const int*)d_in[7];
    float* out = (float*)d_out;

    const int N = in_sizes[0] / FDIM;
    const int E = in_sizes[7] / 2;
    const int Etot = E + N;
    if (N > MAXN || E > MAXE) return;  // scratch sized for the fixed problem

    // Lazily created host-side resources (first call = non-captured correctness
    // run; no device memory involved).
    static cudaStream_t s_side = nullptr;
    static cudaEvent_t  ev_fork = nullptr, ev_join = nullptr;
    if (!s_side) {
        cudaStreamCreateWithFlags(&s_side, cudaStreamNonBlocking);
        cudaEventCreateWithFlags(&ev_fork, cudaEventDisableTiming);
        cudaEventCreateWithFlags(&ev_join, cudaEventDisableTiming);
        cudaFuncSetAttribute(gemm_tc_kernel,
                             cudaFuncAttributeMaxDynamicSharedMemorySize,
                             GEMM_SMEM_BYTES);
    }

    // Fork: CSR build on side stream (depends only on edge_index)
    cudaEventRecord(ev_fork, 0);
    cudaStreamWaitEvent(s_side, ev_fork, 0);

    init_deg_kernel<<<(N + 255) / 256, 256, 0, s_side>>>(N);
    hist_kernel<<<(E + 255) / 256, 256, 0, s_side>>>(ei, E);
    int nChunks = (N + 1023) / 1024;
    scan1_kernel<<<nChunks, 1024, 0, s_side>>>(N);
    scan2_kernel<<<1, 1024, 0, s_side>>>(nChunks);
    scan3_kernel<<<nChunks, 1024, 0, s_side>>>(N, Etot);
    scatter_kernel<<<(Etot + 255) / 256, 256, 0, s_side>>>(ei, E, N);
    cudaEventRecord(ev_join, s_side);

    // Main stream: projection GEMM on tensor cores (tf32, double-buffered)
    transpose_w_kernel<<<256, 256>>>(Wl, Wr);
    gemm_tc_kernel<<<(N + GBM - 1) / GBM, 512, GEMM_SMEM_BYTES>>>(x, bl, br, N);

    // Join, then fused attention softmax + aggregation
    cudaStreamWaitEvent(0, ev_join, 0);
    int nWarpsBlocks = (N * 32 + 255) / 256;
    gat_edge_kernel<<<nWarpsBlocks, 256>>>(att, bias, out, N);
}

// round 7
// speedup vs baseline: 2.0661x; 1.1360x over previous
#include <cuda_runtime.h>
#include <cuda_bf16.h>
#include <cuda_fp16.h>
#include <cstdint>

// Problem constants (fixed by the dataset)
#define MAXN 100000
#define MAXE 1600000
#define MAXETOT (MAXN + MAXE)
#define FDIM 256      // input dim
#define HC   128      // H*C output channels

// ---------------- scratch (device globals; no allocation allowed) -------------
__device__ __half    g_xlh[(size_t)MAXN * HC];  // lin_l projection, fp16 (edge gather)
__device__ float     g_xr[(size_t)MAXN * HC];   // lin_r projection, fp32 (per dst node)
__device__ __half    g_wh[256 * 256];           // W as fp16: [n][k], n<128 -> Wl
__device__ int       g_deg[MAXN];
__device__ int       g_incl[MAXN];
__device__ int       g_sums[1024];
__device__ int       g_rowptr[MAXN + 1];
__device__ int       g_cursor[MAXN];
__device__ int       g_csr[MAXETOT];

// ---------------- fp16 MMA helper ---------------------------------------------
__device__ __forceinline__ void mma_f16(float* d, const unsigned* a, const unsigned* b) {
    asm("mma.sync.aligned.m16n8k16.row.col.f32.f16.f16.f32 "
        "{%0,%1,%2,%3}, {%4,%5,%6,%7}, {%8,%9}, {%0,%1,%2,%3};"
        : "+f"(d[0]), "+f"(d[1]), "+f"(d[2]), "+f"(d[3])
        : "r"(a[0]), "r"(a[1]), "r"(a[2]), "r"(a[3]), "r"(b[0]), "r"(b[1]));
}

// ---------------- W convert to fp16 (tiny: 256x256) ---------------------------
__global__ void convert_w_kernel(const float* __restrict__ Wl,
                                 const float* __restrict__ Wr) {
    int n = blockIdx.x;            // output channel 0..255
    int k = threadIdx.x * 4;       // 0..252
    const float* Wrow = (n < HC) ? &Wl[(size_t)n * FDIM] : &Wr[(size_t)(n - HC) * FDIM];
    float4 v = *(const float4*)&Wrow[k];
    *(__half2*)&g_wh[n * 256 + k]     = __floats2half2_rn(v.x, v.y);
    *(__half2*)&g_wh[n * 256 + k + 2] = __floats2half2_rn(v.z, v.w);
}

// ---------------- fp16 tensor-core GEMM (double-buffered) ---------------------
// y[M,256] = x[M,256] @ Wc^T (+bias); xl half -> g_xlh, xr fp32 -> g_xr.
// BM=128, BN=256, BK=16, 512 threads = 16 warps (4x4), warp tile 32x64 via
// m16n8k16. Smem strides of 24 halfs: frag half2 loads are conflict-free
// (word index 12*r + t is a permutation mod 32 over the warp) and stores are
// 16B-aligned.
#define GBM 128
#define GBK 16
#define AS_H 24
#define BS_H 24
#define AS_HWORDS (GBM * AS_H)              // 3072 halfs
#define BS_HWORDS (256 * BS_H)              // 6144 halfs
#define GEMM_SMEM_BYTES ((2 * AS_HWORDS + 2 * BS_HWORDS) * 2)   // 36864

__global__ __launch_bounds__(512, 1) void gemm_tc_kernel(
    const float* __restrict__ x,
    const float* __restrict__ bl, const float* __restrict__ br,
    int M)
{
    extern __shared__ __half smem_dyn[];
    __half* AsBuf[2] = { smem_dyn, smem_dyn + AS_HWORDS };
    __half* BsBuf[2] = { smem_dyn + 2 * AS_HWORDS, smem_dyn + 2 * AS_HWORDS + BS_HWORDS };

    const int tid  = threadIdx.x;
    const int m0   = blockIdx.x * GBM;
    const int w    = tid >> 5;
    const int lane = tid & 31;
    const int wm   = w >> 2;            // 0..3 -> m offset wm*32
    const int wn   = w & 3;             // 0..3 -> n offset wn*64
    const int gid  = lane >> 2;         // 0..7
    const int tig  = lane & 3;          // 0..3

    float acc[2][8][4];
#pragma unroll
    for (int mt = 0; mt < 2; mt++)
#pragma unroll
        for (int nt = 0; nt < 8; nt++)
#pragma unroll
            for (int c = 0; c < 4; c++) acc[mt][nt][c] = 0.f;

    // A-tile load mapping: thread -> (row, 4-col chunk)
    const int aml = tid >> 2;           // 0..127
    const int ac4 = (tid & 3) * 4;      // 0,4,8,12
    const int gm  = min(m0 + aml, M - 1);
    const float* arow = x + (size_t)gm * FDIM + ac4;

    // B-tile load mapping: 256 n-rows x 16 k halfs = 512 uint4, one per thread
    const int bn  = tid >> 1;           // 0..255
    const int bkh = (tid & 1) * 8;      // 0 or 8

    // ---- preload tile 0 into buffer 0
    {
        float4 av = *(const float4*)(arow);
        uint4  bv = *(const uint4*)&g_wh[bn * 256 + bkh];
        *(__half2*)&AsBuf[0][aml * AS_H + ac4]     = __floats2half2_rn(av.x, av.y);
        *(__half2*)&AsBuf[0][aml * AS_H + ac4 + 2] = __floats2half2_rn(av.z, av.w);
        *(uint4*)&BsBuf[0][bn * BS_H + bkh] = bv;
    }
    __syncthreads();

    const int NIT = FDIM / GBK;   // 16
    for (int it = 0; it < NIT; ++it) {
        const __half* As = AsBuf[it & 1];
        const __half* Bs = BsBuf[it & 1];

        // issue next tile's global loads early (drain under the MMAs below)
        float4 av; uint4 bv;
        if (it + 1 < NIT) {
            const int k0 = (it + 1) * GBK;
            av = *(const float4*)(arow + k0);
            bv = *(const uint4*)&g_wh[bn * 256 + k0 + bkh];
        }

        // fragments + MMAs (one K=16 step per iteration)
        unsigned afr[2][4];
#pragma unroll
        for (int mt = 0; mt < 2; mt++) {
            int r = wm * 32 + mt * 16 + gid;
            afr[mt][0] = *(const unsigned*)&As[r * AS_H + 2 * tig];
            afr[mt][1] = *(const unsigned*)&As[(r + 8) * AS_H + 2 * tig];
            afr[mt][2] = *(const unsigned*)&As[r * AS_H + 2 * tig + 8];
            afr[mt][3] = *(const unsigned*)&As[(r + 8) * AS_H + 2 * tig + 8];
        }
#pragma unroll
        for (int nt = 0; nt < 8; nt++) {
            int cn = wn * 64 + nt * 8 + gid;
            unsigned bfr[2];
            bfr[0] = *(const unsigned*)&Bs[cn * BS_H + 2 * tig];
            bfr[1] = *(const unsigned*)&Bs[cn * BS_H + 2 * tig + 8];
            mma_f16(acc[0][nt], afr[0], bfr);
            mma_f16(acc[1][nt], afr[1], bfr);
        }

        if (it + 1 < NIT) {
            __half* Asn = AsBuf[(it + 1) & 1];
            __half* Bsn = BsBuf[(it + 1) & 1];
            *(__half2*)&Asn[aml * AS_H + ac4]     = __floats2half2_rn(av.x, av.y);
            *(__half2*)&Asn[aml * AS_H + ac4 + 2] = __floats2half2_rn(av.z, av.w);
            *(uint4*)&Bsn[bn * BS_H + bkh] = bv;
            __syncthreads();
        }
    }

    // Epilogue: bias add; xl -> fp16, xr -> fp32
#pragma unroll
    for (int mt = 0; mt < 2; mt++) {
        const int mrow0 = m0 + wm * 32 + mt * 16 + gid;
        const int mrow1 = mrow0 + 8;
#pragma unroll
        for (int nt = 0; nt < 8; nt++) {
            const int n = wn * 64 + nt * 8 + tig * 2;
            if (n < HC) {
                const float b0 = bl[n], b1 = bl[n + 1];
                if (mrow0 < M) {
                    __half2 h = __floats2half2_rn(acc[mt][nt][0] + b0, acc[mt][nt][1] + b1);
                    *(__half2*)&g_xlh[(size_t)mrow0 * HC + n] = h;
                }
                if (mrow1 < M) {
                    __half2 h = __floats2half2_rn(acc[mt][nt][2] + b0, acc[mt][nt][3] + b1);
                    *(__half2*)&g_xlh[(size_t)mrow1 * HC + n] = h;
                }
            } else {
                const int nn = n - HC;
                const float b0 = br[nn], b1 = br[nn + 1];
                if (mrow0 < M) {
                    float2 v; v.x = acc[mt][nt][0] + b0; v.y = acc[mt][nt][1] + b1;
                    *(float2*)&g_xr[(size_t)mrow0 * HC + nn] = v;
                }
                if (mrow1 < M) {
                    float2 v; v.x = acc[mt][nt][2] + b0; v.y = acc[mt][nt][3] + b1;
                    *(float2*)&g_xr[(size_t)mrow1 * HC + nn] = v;
                }
            }
        }
    }
}

// ---------------- CSR build ---------------------------------------------------
__global__ void init_deg_kernel(int N) {
    int i = blockIdx.x * blockDim.x + threadIdx.x;
    if (i < N) g_deg[i] = 1;   // self loop
}

__global__ void hist_kernel(const int* __restrict__ ei, int E) {
    int e = blockIdx.x * blockDim.x + threadIdx.x;
    if (e < E) atomicAdd(&g_deg[ei[E + e]], 1);
}

__global__ void scan1_kernel(int n) {
    __shared__ int s[1024];
    int i = blockIdx.x * 1024 + threadIdx.x;
    int v = (i < n) ? g_deg[i] : 0;
    s[threadIdx.x] = v;
    __syncthreads();
    for (int off = 1; off < 1024; off <<= 1) {
        int t = (threadIdx.x >= off) ? s[threadIdx.x - off] : 0;
        __syncthreads();
        s[threadIdx.x] += t;
        __syncthreads();
    }
    if (i < n) g_incl[i] = s[threadIdx.x];
    if (threadIdx.x == 1023) g_sums[blockIdx.x] = s[1023];
}

__global__ void scan2_kernel(int nc) {
    __shared__ int s[1024];
    int v = (threadIdx.x < nc) ? g_sums[threadIdx.x] : 0;
    s[threadIdx.x] = v;
    __syncthreads();
    for (int off = 1; off < 1024; off <<= 1) {
        int t = (threadIdx.x >= off) ? s[threadIdx.x - off] : 0;
        __syncthreads();
        s[threadIdx.x] += t;
        __syncthreads();
    }
    if (threadIdx.x < nc)
        g_sums[threadIdx.x] = threadIdx.x ? s[threadIdx.x - 1] : 0;
}

__global__ void scan3_kernel(int n, int etot) {
    int i = blockIdx.x * 1024 + threadIdx.x;
    if (i < n) {
        int excl = g_incl[i] - g_deg[i] + g_sums[blockIdx.x];
        g_rowptr[i] = excl;
        g_cursor[i] = excl;
        if (i == n - 1) g_rowptr[n] = etot;
    }
}

__global__ void scatter_kernel(const int* __restrict__ ei, int E, int N) {
    int e = blockIdx.x * blockDim.x + threadIdx.x;
    int etot = E + N;
    if (e >= etot) return;
    int s, d;
    if (e < E) { s = ei[e]; d = ei[E + e]; }
    else       { s = d = e - E; }
    int pos = atomicAdd(&g_cursor[d], 1);
    g_csr[pos] = s;
}

// ---------------- GATv2 edge pass: warp per node, 2 edges/step, pipelined -----
__global__ __launch_bounds__(256) void gat_edge_kernel(
    const float* __restrict__ att, const float* __restrict__ bias,
    float* __restrict__ out, int N)
{
    const int warp = (blockIdx.x * blockDim.x + threadIdx.x) >> 5;
    const int lane = threadIdx.x & 31;
    if (warp >= N) return;
    const int n   = warp;
    const int sub = lane >> 4;      // which edge of the pair
    const int sl  = lane & 15;      // channels [8*sl, 8*sl+8); sl<8 head0, else head1

    float xr[8], at[8];
    {
        float4 v0 = *(const float4*)&g_xr[(size_t)n * HC + sl * 8];
        float4 v1 = *(const float4*)&g_xr[(size_t)n * HC + sl * 8 + 4];
        xr[0]=v0.x; xr[1]=v0.y; xr[2]=v0.z; xr[3]=v0.w;
        xr[4]=v1.x; xr[5]=v1.y; xr[6]=v1.z; xr[7]=v1.w;
        float4 a0 = *(const float4*)&att[sl * 8];
        float4 a1 = *(const float4*)&att[sl * 8 + 4];
        at[0]=a0.x; at[1]=a0.y; at[2]=a0.z; at[3]=a0.w;
        at[4]=a1.x; at[5]=a1.y; at[6]=a1.z; at[7]=a1.w;
    }

    const int base = g_rowptr[n];
    const int end  = g_rowptr[n + 1];

    float denom = 0.f;
    float acc[8];
#pragma unroll
    for (int k = 0; k < 8; k++) acc[k] = 0.f;

    for (int i0 = base; i0 < end; i0 += 32) {
        const int cnt = min(32, end - i0);
        int si = 0;
        if (lane < cnt) si = g_csr[i0 + lane];

        // prefetch pair 0
        int s0 = __shfl_sync(0xffffffffu, si, (sub < cnt) ? sub : 0);
        uint4 hv = *(const uint4*)&g_xlh[(size_t)s0 * HC + sl * 8];

#pragma unroll 1
        for (int jp = 0; jp < cnt; jp += 2) {
            const bool valid = (jp + sub) < cnt;

            // prefetch next pair's row segment (overlaps compute below)
            const int nidx = jp + 2 + sub;
            const int sn = __shfl_sync(0xffffffffu, si, (nidx < cnt) ? nidx : 0);
            uint4 hvn = hv;
            if (jp + 2 < cnt) hvn = *(const uint4*)&g_xlh[(size_t)sn * HC + sl * 8];

            float f[8];
            {
                float2 p0 = __half22float2(*(__half2*)&hv.x);
                float2 p1 = __half22float2(*(((__half2*)&hv.x) + 1));
                float2 p2 = __half22float2(*(__half2*)&hv.z);
                float2 p3 = __half22float2(*(((__half2*)&hv.z) + 1));
                f[0]=p0.x; f[1]=p0.y; f[2]=p1.x; f[3]=p1.y;
                f[4]=p2.x; f[5]=p2.y; f[6]=p3.x; f[7]=p3.y;
            }

            float part = 0.f;
#pragma unroll
            for (int k = 0; k < 8; k++) {
                float e = f[k] + xr[k];
                float l = e > 0.f ? e : 0.2f * e;
                part = fmaf(l, at[k], part);
            }
            // reduce over 8-lane head group
            part += __shfl_xor_sync(0xffffffffu, part, 1);
            part += __shfl_xor_sync(0xffffffffu, part, 2);
            part += __shfl_xor_sync(0xffffffffu, part, 4);

            float p = valid ? __expf(part) : 0.f;
            denom += p;
#pragma unroll
            for (int k = 0; k < 8; k++) acc[k] = fmaf(p, f[k], acc[k]);

            hv = hvn;
        }
    }

    // combine the two edge-halves of the warp
    denom += __shfl_xor_sync(0xffffffffu, denom, 16);
#pragma unroll
    for (int k = 0; k < 8; k++) acc[k] += __shfl_xor_sync(0xffffffffu, acc[k], 16);

    if (sub == 0) {
        const float rd = 1.0f / denom;
        float4 b0 = *(const float4*)&bias[sl * 8];
        float4 b1 = *(const float4*)&bias[sl * 8 + 4];
        float4 o0, o1;
        o0.x = fmaf(acc[0], rd, b0.x); o0.y = fmaf(acc[1], rd, b0.y);
        o0.z = fmaf(acc[2], rd, b0.z); o0.w = fmaf(acc[3], rd, b0.w);
        o1.x = fmaf(acc[4], rd, b1.x); o1.y = fmaf(acc[5], rd, b1.y);
        o1.z = fmaf(acc[6], rd, b1.z); o1.w = fmaf(acc[7], rd, b1.w);
        *(float4*)&out[(size_t)n * HC + sl * 8]     = o0;
        *(float4*)&out[(size_t)n * HC + sl * 8 + 4] = o1;
    }
}

// ---------------- launch ------------------------------------------------------
extern "C" void kernel_launch(void* const* d_in, const int* in_sizes, int n_in,
                              void* d_out, int out_size)
{
    const float* x    = (const float*)d_in[0];
    const float* Wl   = (const float*)d_in[1];
    const float* bl   = (const float*)d_in[2];
    const float* Wr   = (const float*)d_in[3];
    const float* br   = (const float*)d_in[4];
    const float* att  = (const float*)d_in[5];
    const float* bias = (const float*)d_in[6];
    const int*   ei   = (const int*)d_in[7];
    float* out = (float*)d_out;

    const int N = in_sizes[0] / FDIM;
    const int E = in_sizes[7] / 2;
    const int Etot = E + N;
    if (N > MAXN || E > MAXE) return;  // scratch sized for the fixed problem

    // Lazily created host-side resources (first call = non-captured correctness
    // run; no device memory involved).
    static cudaStream_t s_side = nullptr;
    static cudaEvent_t  ev_fork = nullptr, ev_join = nullptr;
    if (!s_side) {
        cudaStreamCreateWithFlags(&s_side, cudaStreamNonBlocking);
        cudaEventCreateWithFlags(&ev_fork, cudaEventDisableTiming);
        cudaEventCreateWithFlags(&ev_join, cudaEventDisableTiming);
        cudaFuncSetAttribute(gemm_tc_kernel,
                             cudaFuncAttributeMaxDynamicSharedMemorySize,
                             GEMM_SMEM_BYTES);
    }

    // Fork: CSR build on side stream (depends only on edge_index)
    cudaEventRecord(ev_fork, 0);
    cudaStreamWaitEvent(s_side, ev_fork, 0);

    init_deg_kernel<<<(N + 255) / 256, 256, 0, s_side>>>(N);
    hist_kernel<<<(E + 255) / 256, 256, 0, s_side>>>(ei, E);
    int nChunks = (N + 1023) / 1024;
    scan1_kernel<<<nChunks, 1024, 0, s_side>>>(N);
    scan2_kernel<<<1, 1024, 0, s_side>>>(nChunks);
    scan3_kernel<<<nChunks, 1024, 0, s_side>>>(N, Etot);
    scatter_kernel<<<(Etot + 255) / 256, 256, 0, s_side>>>(ei, E, N);
    cudaEventRecord(ev_join, s_side);

    // Main stream: W convert + projection GEMM on tensor cores (fp16)
    convert_w_kernel<<<256, 64>>>(Wl, Wr);
    gemm_tc_kernel<<<(N + GBM - 1) / GBM, 512, GEMM_SMEM_BYTES>>>(x, bl, br, N);

    // Join, then fused attention softmax + aggregation
    cudaStreamWaitEvent(0, ev_join, 0);
    int nWarpsBlocks = (N * 32 + 255) / 256;
    gat_edge_kernel<<<nWarpsBlocks, 256>>>(att, bias, out, N);
}